// round 14
// baseline (speedup 1.0000x reference)
#include <cuda_runtime.h>
#include <cuda_fp16.h>
#include <cstdint>
#include <cstddef>

// Problem constants
#define B_   32
#define L_   512
#define H_   8
#define DH   64
#define DIN  512
#define HB   (H_ * B_)          // 256

// exp(s/8) == exp2(s * 0.125 * log2(e)); folded into Q at projection time.
#define EXPC 0.18033688011112042f
#define ONES_H2 0x3C003C00u     // half2(1.0, 1.0)

// ---------------------------------------------------------------------------
// Scratch (static device globals)
// ---------------------------------------------------------------------------
__device__ __half g_Ah[(size_t)2 * 16384 * 512];   // fp16 copies of query,key
__device__ __half g_Wt[(size_t)3 * 512 * 512];     // W^T (n-major, k contiguous) fp16
__device__ __half g_Qh[(size_t)HB * L_ * DH];      // head-split Q*EXPC [hb][l][d]
__device__ __half g_Kh[(size_t)HB * L_ * DH];      // head-split K  [hb][l][d]
__device__ __half g_Vt[(size_t)HB * DH * L_];      // head-split V transposed [hb][d][l]
__device__ float  g_km[B_ * L_];                   // key padding mask (0/1)
__device__ float  g_qm[B_ * L_];                   // query padding mask (0/1)
__device__ int    g_kmflag[B_ * 8];                // 1 if km all-ones in 64-col group

// ---------------------------------------------------------------------------
// Helpers
// ---------------------------------------------------------------------------
__device__ __forceinline__ void mma_f16(float c[4],
                                        uint32_t a0, uint32_t a1, uint32_t a2, uint32_t a3,
                                        uint32_t b0, uint32_t b1) {
    asm volatile(
        "mma.sync.aligned.m16n8k16.row.col.f32.f16.f16.f32 "
        "{%0,%1,%2,%3}, {%4,%5,%6,%7}, {%8,%9}, {%0,%1,%2,%3};\n"
        : "+f"(c[0]), "+f"(c[1]), "+f"(c[2]), "+f"(c[3])
        : "r"(a0), "r"(a1), "r"(a2), "r"(a3), "r"(b0), "r"(b1));
}

__device__ __forceinline__ uint32_t h2u(float lo, float hi) {
    __half2 h = __floats2half2_rn(lo, hi);
    return *(uint32_t*)&h;
}

__device__ __forceinline__ uint32_t ex2h2(uint32_t x) {
    uint32_t r;
    asm("ex2.approx.f16x2 %0, %1;" : "=r"(r) : "r"(x));
    return r;
}

__device__ __forceinline__ void ldsm4(uint32_t& r0, uint32_t& r1, uint32_t& r2, uint32_t& r3,
                                      uint32_t addr) {
    asm volatile("ldmatrix.sync.aligned.m8n8.x4.shared.b16 {%0,%1,%2,%3}, [%4];"
                 : "=r"(r0), "=r"(r1), "=r"(r2), "=r"(r3) : "r"(addr));
}

__device__ __forceinline__ void cp16(uint32_t dst, const void* src) {
    asm volatile("cp.async.cg.shared.global [%0], [%1], 16;" :: "r"(dst), "l"(src));
}
#define CP_COMMIT() asm volatile("cp.async.commit_group;")
#define CP_WAIT0()  asm volatile("cp.async.wait_group 0;")
#define CP_WAIT1()  asm volatile("cp.async.wait_group 1;")

// ---------------------------------------------------------------------------
// Kernel 1: padding masks + fp32 -> fp16 conversion of query/key.
// ---------------------------------------------------------------------------
__global__ __launch_bounds__(256) void prep_qk_kernel(const float* __restrict__ query,
                                                      const float* __restrict__ key) {
    int t    = blockIdx.x * blockDim.x + threadIdx.x;
    int warp = t >> 5;
    int lane = t & 31;
    int which = warp >> 14;
    int row   = warp & 16383;
    const float4* src = (const float4*)((which ? key : query) + (size_t)row * DIN);
    __half* dst = g_Ah + ((size_t)which * 16384 + row) * 512;
    float s = 0.f;
#pragma unroll
    for (int i = 0; i < 4; i++) {
        float4 v = src[lane + 32 * i];
        s += (v.x + v.y) + (v.z + v.w);
        __half2 h0 = __floats2half2_rn(v.x, v.y);
        __half2 h1 = __floats2half2_rn(v.z, v.w);
        uint2 u = make_uint2(*(uint32_t*)&h0, *(uint32_t*)&h1);
        *(uint2*)(dst + (size_t)(lane + 32 * i) * 4) = u;
    }
#pragma unroll
    for (int o = 16; o; o >>= 1) s += __shfl_xor_sync(0xffffffffu, s, o);
    if (lane == 0) (which ? g_km : g_qm)[row] = (s != 0.f) ? 1.f : 0.f;
}

// ---------------------------------------------------------------------------
// Kernel 1b: per-(batch, 64-col group) kmask all-ones flags. 1 block, 256 thr.
// ---------------------------------------------------------------------------
__global__ void prep_flags_kernel() {
    int t = threadIdx.x;           // t = b*8 + g
    int b = t >> 3, g = t & 7;
    int ok = 1;
#pragma unroll 8
    for (int i = 0; i < 64; i++)
        ok &= (g_km[b * 512 + g * 64 + i] != 0.f) ? 1 : 0;
    g_kmflag[t] = ok;
}

// ---------------------------------------------------------------------------
// Kernel 2: W transpose + convert.  g_Wt[z][n][k] = half(W_z[k][n]).
// ---------------------------------------------------------------------------
__global__ __launch_bounds__(256) void prep_w_kernel(const float* __restrict__ Wq,
                                                     const float* __restrict__ Wk,
                                                     const float* __restrict__ Wv) {
    const int z  = blockIdx.z;
    const float* W = (z == 0) ? Wq : (z == 1) ? Wk : Wv;
    const int k0 = blockIdx.x * 32;
    const int n0 = blockIdx.y * 32;
    __shared__ float ts[32][33];
    int e = threadIdx.x;
    {
        int kr = e >> 3, c4 = e & 7;
        float4 v = *(const float4*)(W + (size_t)(k0 + kr) * 512 + n0 + c4 * 4);
        ts[kr][c4 * 4 + 0] = v.x;
        ts[kr][c4 * 4 + 1] = v.y;
        ts[kr][c4 * 4 + 2] = v.z;
        ts[kr][c4 * 4 + 3] = v.w;
    }
    __syncthreads();
    {
        int n = e >> 3, g = e & 7;
        __half2 h0 = __floats2half2_rn(ts[g * 4 + 0][n], ts[g * 4 + 1][n]);
        __half2 h1 = __floats2half2_rn(ts[g * 4 + 2][n], ts[g * 4 + 3][n]);
        uint2 u = make_uint2(*(uint32_t*)&h0, *(uint32_t*)&h1);
        *(uint2*)(g_Wt + ((size_t)z * 512 + n0 + n) * 512 + k0 + g * 4) = u;
    }
}

// ---------------------------------------------------------------------------
// Kernel 3: projections, fp16 mma + ldmatrix + 3-stage cp.async pipeline.
// K-step 64, 8 iterations. DYNAMIC smem 96KB: A[3][128][64h], B[3][128][64h].
// Rows 128B (8 chunks of 16B), XOR swizzle phys = c ^ (row&7).
// z==0 (Q) epilogue folds the softmax scale EXPC into the stored values.
// z==2 (V) epilogue routed through smem for coalesced transposed stores.
// ---------------------------------------------------------------------------
#define PROJ_SMEM_BYTES (size_t)98304

__global__ __launch_bounds__(256, 2) void proj_kernel() {
    const int z = blockIdx.z;
    const __half* A  = g_Ah + (size_t)(z ? 1 : 0) * 16384 * 512;
    const __half* Wt = g_Wt + (size_t)z * 512 * 512;

    const int m0 = blockIdx.y * 128;
    const int n0 = blockIdx.x * 128;

    extern __shared__ __align__(16) char psm[];
    const uint32_t aBase = (uint32_t)__cvta_generic_to_shared(psm);
    const uint32_t bBase = aBase + 3 * 16384;

    const int tid  = threadIdx.x;
    const int lane = tid & 31;
    const int wid  = tid >> 5;
    const int wm   = wid & 3;
    const int wn   = wid >> 2;

    float acc[2][8][4];
#pragma unroll
    for (int i = 0; i < 2; i++)
#pragma unroll
        for (int j = 0; j < 8; j++)
#pragma unroll
            for (int r = 0; r < 4; r++) acc[i][j][r] = 0.f;

    // staging: per k-step-64, 1024 16B-chunks per matrix; 4 per thread each.
    const int srow = tid >> 3;          // 0..31, +32*rr
    const int sc   = tid & 7;           // logical chunk 0..7
#define PROJ_ISSUE(kk, buf)                                                          \
    {                                                                                \
        _Pragma("unroll")                                                            \
        for (int rr = 0; rr < 4; rr++) {                                             \
            int row  = srow + rr * 32;                                               \
            int phys = sc ^ (row & 7);                                               \
            cp16(aBase + (buf) * 16384 + row * 128 + phys * 16,                      \
                 A + (size_t)(m0 + row) * 512 + (kk) * 64 + sc * 8);                 \
            cp16(bBase + (buf) * 16384 + row * 128 + phys * 16,                      \
                 Wt + (size_t)(n0 + row) * 512 + (kk) * 64 + sc * 8);                \
        }                                                                            \
    }

    PROJ_ISSUE(0, 0);
    CP_COMMIT();
    PROJ_ISSUE(1, 1);
    CP_COMMIT();

    for (int it = 0; it < 8; it++) {
        if (it + 1 < 8) { CP_WAIT1(); } else { CP_WAIT0(); }
        __syncthreads();
        if (it + 2 < 8) {
            PROJ_ISSUE(it + 2, (it + 2) % 3);
            CP_COMMIT();
        }
        const int buf = it % 3;

#pragma unroll
        for (int ss = 0; ss < 2; ss++) {
            uint32_t a[2][2][4];   // [kg][mi][]
#pragma unroll
            for (int kg = 0; kg < 2; kg++)
#pragma unroll
                for (int mi = 0; mi < 2; mi++) {
                    int row  = wm * 32 + mi * 16 + (lane & 15);
                    int c    = ss * 4 + kg * 2 + (lane >> 4);
                    int phys = c ^ (row & 7);
                    ldsm4(a[kg][mi][0], a[kg][mi][1], a[kg][mi][2], a[kg][mi][3],
                          aBase + buf * 16384 + row * 128 + phys * 16);
                }
#pragma unroll
            for (int ni = 0; ni < 8; ni++) {
                int row  = wn * 64 + ni * 8 + (lane & 7);
                int c    = ss * 4 + (lane >> 3);
                int phys = c ^ (row & 7);
                uint32_t b0, b1, b2, b3;
                ldsm4(b0, b1, b2, b3, bBase + buf * 16384 + row * 128 + phys * 16);
                mma_f16(acc[0][ni], a[0][0][0], a[0][0][1], a[0][0][2], a[0][0][3], b0, b1);
                mma_f16(acc[1][ni], a[0][1][0], a[0][1][1], a[0][1][2], a[0][1][3], b0, b1);
                mma_f16(acc[0][ni], a[1][0][0], a[1][0][1], a[1][0][2], a[1][0][3], b2, b3);
                mma_f16(acc[1][ni], a[1][1][0], a[1][1][1], a[1][1][2], a[1][1][3], b2, b3);
            }
        }
    }
#undef PROJ_ISSUE

    const int gid = lane >> 2;
    const int tig = lane & 3;

    if (z == 2) {
        // ---- V epilogue: stage [n][l] in smem, then coalesced 16B stores ----
        __syncthreads();   // all LDSM of last tile done; staging smem reusable
        __half* tsm = (__half*)psm;           // [128 n][136 l-stride]
#pragma unroll
        for (int mi = 0; mi < 2; mi++)
#pragma unroll
            for (int ni = 0; ni < 8; ni++) {
                int lr = wm * 32 + mi * 16 + gid;          // local row (l)
                int nc = wn * 64 + ni * 8 + tig * 2;       // local col (n)
#pragma unroll
                for (int rr = 0; rr < 2; rr++) {
                    int lrow = lr + rr * 8;
                    tsm[(nc + 0) * 136 + lrow] = __float2half_rn(acc[mi][ni][rr * 2 + 0]);
                    tsm[(nc + 1) * 136 + lrow] = __float2half_rn(acc[mi][ni][rr * 2 + 1]);
                }
            }
        __syncthreads();
        const int bb = m0 >> 9;
        const int l0 = m0 & 511;
#pragma unroll
        for (int itx = 0; itx < 8; itx++) {
            int e = tid + itx * 256;
            int n = e >> 4, cc = e & 15;
            uint4 v = *(const uint4*)&tsm[n * 136 + cc * 8];
            int gcol = n0 + n;
            int hh = gcol >> 6, dd = gcol & 63;
            *(uint4*)(g_Vt + ((size_t)(hh * 32 + bb) * 64 + dd) * 512 + l0 + cc * 8) = v;
        }
    } else {
        __half* dst = (z == 0) ? g_Qh : g_Kh;
        const float esc = (z == 0) ? EXPC : 1.f;   // fold softmax scale into Q
#pragma unroll
        for (int mi = 0; mi < 2; mi++)
#pragma unroll
            for (int ni = 0; ni < 8; ni++) {
                int gm = m0 + wm * 32 + mi * 16 + gid;
                int gn = n0 + wn * 64 + ni * 8 + tig * 2;
                int h = gn >> 6, d = gn & 63;
#pragma unroll
                for (int rr = 0; rr < 2; rr++) {
                    int row = gm + rr * 8;
                    int bb = row >> 9, ll = row & 511;
                    __half2 hv = __floats2half2_rn(acc[mi][ni][rr * 2 + 0] * esc,
                                                   acc[mi][ni][rr * 2 + 1] * esc);
                    *(__half2*)(dst + ((size_t)(h * 32 + bb) * 512 + ll) * 64 + d) = hv;
                }
            }
    }
}

// ---------------------------------------------------------------------------
// Kernel 4: fused flash attention. Q pre-scaled by EXPC, so S is already in
// the exp2 domain: fast path feeds mma output straight to ex2.approx.f16x2.
// Row sums via MMA against a constant all-ones B fragment. 2-stage KV prefetch.
// ---------------------------------------------------------------------------
#define ATTN_SMEM_BYTES (size_t)((128 * 72 + 2 * 2 * 64 * 72) * 2)   // 55296

__global__ __launch_bounds__(256, 2) void attn_kernel(const float* __restrict__ query,
                                                      float* __restrict__ out) {
    const int hb = blockIdx.y;
    const int h  = hb >> 5;
    const int b  = hb & 31;
    const int m0 = blockIdx.x * 128;

    const __half* Qh = g_Qh + (size_t)hb * L_ * DH;
    const __half* Kh = g_Kh + (size_t)hb * L_ * DH;
    const __half* Vt = g_Vt + (size_t)hb * DH * L_;

    extern __shared__ __align__(16) __half dynsm[];
    const uint32_t qBase  = (uint32_t)__cvta_generic_to_shared(dynsm);
    const uint32_t kvBase = qBase + 128 * 72 * 2;
    const int KV_STAGE = 2 * 64 * 72 * 2;
    const int KV_VOFF  = 64 * 72 * 2;

    const int tid  = threadIdx.x;
    const int lane = tid & 31;
    const int wid  = tid >> 5;
    const int gid  = lane >> 2;
    const int tig  = lane & 3;
    const int q0   = m0 + wid * 16 + gid;
    const int q1   = q0 + 8;

    const int srow = tid >> 3;
    const int sc   = tid & 7;

#pragma unroll
    for (int r = 0; r < 4; r++) {
        int row = srow + r * 32;
        cp16(qBase + row * 144 + sc * 16, Qh + (size_t)(m0 + row) * 64 + sc * 8);
    }
    CP_COMMIT();

#define ATTN_ISSUE_KV(k0, st)                                                        \
    {                                                                                \
        _Pragma("unroll")                                                            \
        for (int r = 0; r < 2; r++) {                                                \
            int kc = srow + r * 32;                                                  \
            cp16(kvBase + (st) * KV_STAGE + kc * 144 + sc * 16,                      \
                 Kh + (size_t)((k0) + kc) * 64 + sc * 8);                            \
            cp16(kvBase + (st) * KV_STAGE + KV_VOFF + kc * 144 + sc * 16,            \
                 Vt + (size_t)kc * 512 + (k0) + sc * 8);                             \
        }                                                                            \
    }

    ATTN_ISSUE_KV(0, 0);
    CP_COMMIT();

    CP_WAIT1();
    __syncthreads();

    uint32_t Qa[4][4];
    {
        int row = wid * 16 + (lane & 15);
#pragma unroll
        for (int kg = 0; kg < 4; kg++) {
            int chunk = kg * 2 + (lane >> 4);
            ldsm4(Qa[kg][0], Qa[kg][1], Qa[kg][2], Qa[kg][3],
                  qBase + row * 144 + chunk * 16);
        }
    }

    float o[8][4];
#pragma unroll
    for (int di = 0; di < 8; di++)
#pragma unroll
        for (int j = 0; j < 4; j++) o[di][j] = 0.f;
    float lacc[4] = {0.f, 0.f, 0.f, 0.f};

    const int nkt = (m0 >> 6) + 2;
    for (int kt = 0; kt < nkt; kt++) {
        const int k0 = kt * 64;
        const int st = kt & 1;
        CP_WAIT0();
        __syncthreads();
        if (kt + 1 < nkt) {
            ATTN_ISSUE_KV(k0 + 64, st ^ 1);
            CP_COMMIT();
        }

        const uint32_t kB = kvBase + st * KV_STAGE;
        float s[8][4];
#pragma unroll
        for (int ni = 0; ni < 8; ni++)
#pragma unroll
            for (int j = 0; j < 4; j++) s[ni][j] = 0.f;
#pragma unroll
        for (int ni = 0; ni < 8; ni++) {
            uint32_t addr = kB + (ni * 8 + (lane & 7)) * 144 + (lane >> 3) * 16;
            uint32_t b0, b1, b2, b3, c0, c1, c2, c3;
            ldsm4(b0, b1, b2, b3, addr);
            ldsm4(c0, c1, c2, c3, addr + 64);
            mma_f16(s[ni], Qa[0][0], Qa[0][1], Qa[0][2], Qa[0][3], b0, b1);
            mma_f16(s[ni], Qa[1][0], Qa[1][1], Qa[1][2], Qa[1][3], b2, b3);
            mma_f16(s[ni], Qa[2][0], Qa[2][1], Qa[2][2], Qa[2][3], c0, c1);
            mma_f16(s[ni], Qa[3][0], Qa[3][1], Qa[3][2], Qa[3][3], c2, c3);
        }

        // Q was pre-scaled by EXPC, so s is already the exp2 exponent.
        // Interior tiles need no per-element work at all; boundary/masked
        // tiles just select -1e9 (half cvt -> -inf, ex2 -> exact 0).
        const bool fast = g_kmflag[b * 8 + kt] && (k0 + 63 <= m0 + wid * 16);
        if (!fast) {
#pragma unroll
            for (int ni = 0; ni < 8; ni++) {
                int c0i = k0 + ni * 8 + tig * 2;
                bool km0 = g_km[b * 512 + c0i] != 0.f;
                bool km1 = g_km[b * 512 + c0i + 1] != 0.f;
                if (!(c0i <= q0     && km0)) s[ni][0] = -1e9f;
                if (!(c0i + 1 <= q0 && km1)) s[ni][1] = -1e9f;
                if (!(c0i <= q1     && km0)) s[ni][2] = -1e9f;
                if (!(c0i + 1 <= q1 && km1)) s[ni][3] = -1e9f;
            }
        }

        uint32_t Pa[4][4];
#pragma unroll
        for (int kg = 0; kg < 4; kg++) {
            Pa[kg][0] = ex2h2(h2u(s[2 * kg][0],     s[2 * kg][1]));
            Pa[kg][1] = ex2h2(h2u(s[2 * kg][2],     s[2 * kg][3]));
            Pa[kg][2] = ex2h2(h2u(s[2 * kg + 1][0], s[2 * kg + 1][1]));
            Pa[kg][3] = ex2h2(h2u(s[2 * kg + 1][2], s[2 * kg + 1][3]));
            mma_f16(lacc, Pa[kg][0], Pa[kg][1], Pa[kg][2], Pa[kg][3],
                    ONES_H2, ONES_H2);
        }

        const uint32_t vB = kB + KV_VOFF;
#pragma unroll
        for (int di = 0; di < 8; di++) {
            uint32_t addr = vB + (di * 8 + (lane & 7)) * 144 + (lane >> 3) * 16;
            uint32_t b0, b1, b2, b3, c0, c1, c2, c3;
            ldsm4(b0, b1, b2, b3, addr);
            ldsm4(c0, c1, c2, c3, addr + 64);
            mma_f16(o[di], Pa[0][0], Pa[0][1], Pa[0][2], Pa[0][3], b0, b1);
            mma_f16(o[di], Pa[1][0], Pa[1][1], Pa[1][2], Pa[1][3], b2, b3);
            mma_f16(o[di], Pa[2][0], Pa[2][1], Pa[2][2], Pa[2][3], c0, c1);
            mma_f16(o[di], Pa[3][0], Pa[3][1], Pa[3][2], Pa[3][3], c2, c3);
        }
    }
#undef ATTN_ISSUE_KV

    float sc0 = g_qm[b * 512 + q0] / lacc[0];
    float sc1 = g_qm[b * 512 + q1] / lacc[2];
#pragma unroll
    for (int di = 0; di < 8; di++) {
        int col = h * 64 + di * 8 + tig * 2;
        size_t i0 = ((size_t)(b * 512 + q0)) * 512 + col;
        size_t i1 = ((size_t)(b * 512 + q1)) * 512 + col;
        float2 qv0 = *(const float2*)(query + i0);
        float2 qv1 = *(const float2*)(query + i1);
        float2 w0, w1;
        w0.x = o[di][0] * sc0 + qv0.x;
        w0.y = o[di][1] * sc0 + qv0.y;
        w1.x = o[di][2] * sc1 + qv1.x;
        w1.y = o[di][3] * sc1 + qv1.y;
        *(float2*)(out + i0) = w0;
        *(float2*)(out + i1) = w1;
    }
}

// ---------------------------------------------------------------------------
// Launch
// ---------------------------------------------------------------------------
extern "C" void kernel_launch(void* const* d_in, const int* in_sizes, int n_in,
                              void* d_out, int out_size) {
    const float* query = (const float*)d_in[0];
    const float* key   = (const float*)d_in[1];
    const float* Wq    = (const float*)d_in[2];
    const float* Wk    = (const float*)d_in[3];
    const float* Wv    = (const float*)d_in[4];
    float* out = (float*)d_out;

    // Immediate (non-stream) API: capture-safe, idempotent, no allocation.
    cudaFuncSetAttribute(attn_kernel, cudaFuncAttributeMaxDynamicSharedMemorySize,
                         (int)ATTN_SMEM_BYTES);
    cudaFuncSetAttribute(proj_kernel, cudaFuncAttributeMaxDynamicSharedMemorySize,
                         (int)PROJ_SMEM_BYTES);

    prep_qk_kernel<<<4096, 256>>>(query, key);
    prep_flags_kernel<<<1, 256>>>();
    prep_w_kernel<<<dim3(16, 16, 3), 256>>>(Wq, Wk, Wv);
    proj_kernel<<<dim3(4, 128, 3), 256, PROJ_SMEM_BYTES>>>();
    attn_kernel<<<dim3(4, HB), 256, ATTN_SMEM_BYTES>>>(query, out);
}

// round 15
// speedup vs baseline: 1.0123x; 1.0123x over previous
#include <cuda_runtime.h>
#include <cuda_fp16.h>
#include <cstdint>
#include <cstddef>

// Problem constants
#define B_   32
#define L_   512
#define H_   8
#define DH   64
#define DIN  512
#define HB   (H_ * B_)          // 256

// exp(s/8) == exp2(s * 0.125 * log2(e)); folded into Q at projection time.
#define EXPC 0.18033688011112042f
#define ONES_H2 0x3C003C00u     // half2(1.0, 1.0)

// ---------------------------------------------------------------------------
// Scratch (static device globals)
// ---------------------------------------------------------------------------
__device__ __half g_Ah[(size_t)2 * 16384 * 512];   // fp16 copies of query,key
__device__ __half g_Wt[(size_t)3 * 512 * 512];     // W^T (n-major, k contiguous) fp16
__device__ __half g_Qh[(size_t)HB * L_ * DH];      // head-split Q*EXPC [hb][l][d]
__device__ __half g_Kh[(size_t)HB * L_ * DH];      // head-split K  [hb][l][d]
__device__ __half g_Vt[(size_t)HB * DH * L_];      // head-split V transposed [hb][d][l]
__device__ float  g_km[B_ * L_];                   // key padding mask (0/1)
__device__ float  g_qm[B_ * L_];                   // query padding mask (0/1)
__device__ int    g_kmflag[B_ * 8];                // 1 if km all-ones in 64-col group

// ---------------------------------------------------------------------------
// Helpers
// ---------------------------------------------------------------------------
__device__ __forceinline__ void mma_f16(float c[4],
                                        uint32_t a0, uint32_t a1, uint32_t a2, uint32_t a3,
                                        uint32_t b0, uint32_t b1) {
    asm volatile(
        "mma.sync.aligned.m16n8k16.row.col.f32.f16.f16.f32 "
        "{%0,%1,%2,%3}, {%4,%5,%6,%7}, {%8,%9}, {%0,%1,%2,%3};\n"
        : "+f"(c[0]), "+f"(c[1]), "+f"(c[2]), "+f"(c[3])
        : "r"(a0), "r"(a1), "r"(a2), "r"(a3), "r"(b0), "r"(b1));
}

__device__ __forceinline__ uint32_t h2u(float lo, float hi) {
    __half2 h = __floats2half2_rn(lo, hi);
    return *(uint32_t*)&h;
}

__device__ __forceinline__ uint32_t ex2h2(uint32_t x) {
    uint32_t r;
    asm("ex2.approx.f16x2 %0, %1;" : "=r"(r) : "r"(x));
    return r;
}

__device__ __forceinline__ void ldsm4(uint32_t& r0, uint32_t& r1, uint32_t& r2, uint32_t& r3,
                                      uint32_t addr) {
    asm volatile("ldmatrix.sync.aligned.m8n8.x4.shared.b16 {%0,%1,%2,%3}, [%4];"
                 : "=r"(r0), "=r"(r1), "=r"(r2), "=r"(r3) : "r"(addr));
}

__device__ __forceinline__ void cp16(uint32_t dst, const void* src) {
    asm volatile("cp.async.cg.shared.global [%0], [%1], 16;" :: "r"(dst), "l"(src));
}
#define CP_COMMIT() asm volatile("cp.async.commit_group;")
#define CP_WAIT0()  asm volatile("cp.async.wait_group 0;")
#define CP_WAIT1()  asm volatile("cp.async.wait_group 1;")

// ---------------------------------------------------------------------------
// Kernel 1: padding masks + fp32 -> fp16 conversion of query/key.
// ---------------------------------------------------------------------------
__global__ __launch_bounds__(256) void prep_qk_kernel(const float* __restrict__ query,
                                                      const float* __restrict__ key) {
    int t    = blockIdx.x * blockDim.x + threadIdx.x;
    int warp = t >> 5;
    int lane = t & 31;
    int which = warp >> 14;
    int row   = warp & 16383;
    const float4* src = (const float4*)((which ? key : query) + (size_t)row * DIN);
    __half* dst = g_Ah + ((size_t)which * 16384 + row) * 512;
    float s = 0.f;
#pragma unroll
    for (int i = 0; i < 4; i++) {
        float4 v = src[lane + 32 * i];
        s += (v.x + v.y) + (v.z + v.w);
        __half2 h0 = __floats2half2_rn(v.x, v.y);
        __half2 h1 = __floats2half2_rn(v.z, v.w);
        uint2 u = make_uint2(*(uint32_t*)&h0, *(uint32_t*)&h1);
        *(uint2*)(dst + (size_t)(lane + 32 * i) * 4) = u;
    }
#pragma unroll
    for (int o = 16; o; o >>= 1) s += __shfl_xor_sync(0xffffffffu, s, o);
    if (lane == 0) (which ? g_km : g_qm)[row] = (s != 0.f) ? 1.f : 0.f;
}

// ---------------------------------------------------------------------------
// Kernel 1b: per-(batch, 64-col group) kmask all-ones flags. 1 block, 256 thr.
// ---------------------------------------------------------------------------
__global__ void prep_flags_kernel() {
    int t = threadIdx.x;           // t = b*8 + g
    int b = t >> 3, g = t & 7;
    int ok = 1;
#pragma unroll 8
    for (int i = 0; i < 64; i++)
        ok &= (g_km[b * 512 + g * 64 + i] != 0.f) ? 1 : 0;
    g_kmflag[t] = ok;
}

// ---------------------------------------------------------------------------
// Kernel 2: W transpose + convert.  g_Wt[z][n][k] = half(W_z[k][n]).
// ---------------------------------------------------------------------------
__global__ __launch_bounds__(256) void prep_w_kernel(const float* __restrict__ Wq,
                                                     const float* __restrict__ Wk,
                                                     const float* __restrict__ Wv) {
    const int z  = blockIdx.z;
    const float* W = (z == 0) ? Wq : (z == 1) ? Wk : Wv;
    const int k0 = blockIdx.x * 32;
    const int n0 = blockIdx.y * 32;
    __shared__ float ts[32][33];
    int e = threadIdx.x;
    {
        int kr = e >> 3, c4 = e & 7;
        float4 v = *(const float4*)(W + (size_t)(k0 + kr) * 512 + n0 + c4 * 4);
        ts[kr][c4 * 4 + 0] = v.x;
        ts[kr][c4 * 4 + 1] = v.y;
        ts[kr][c4 * 4 + 2] = v.z;
        ts[kr][c4 * 4 + 3] = v.w;
    }
    __syncthreads();
    {
        int n = e >> 3, g = e & 7;
        __half2 h0 = __floats2half2_rn(ts[g * 4 + 0][n], ts[g * 4 + 1][n]);
        __half2 h1 = __floats2half2_rn(ts[g * 4 + 2][n], ts[g * 4 + 3][n]);
        uint2 u = make_uint2(*(uint32_t*)&h0, *(uint32_t*)&h1);
        *(uint2*)(g_Wt + ((size_t)z * 512 + n0 + n) * 512 + k0 + g * 4) = u;
    }
}

// ---------------------------------------------------------------------------
// Kernel 3: projections, fp16 mma + ldmatrix + cp.async double buffer.
// K-step 64 (8 iterations). DYNAMIC smem 64KB: A[2][128][64h], B[2][128][64h]
// (the 2-stage config measured fastest; 3-stage regressed via L1-capacity loss).
// Rows 128B (8 chunks of 16B), XOR swizzle phys = c ^ (row&7).
// z==0 (Q) epilogue folds the softmax scale EXPC into the stored values.
// z==2 (V) epilogue routed through smem for coalesced transposed stores.
// ---------------------------------------------------------------------------
#define PROJ_SMEM_BYTES (size_t)65536

__global__ __launch_bounds__(256, 2) void proj_kernel() {
    const int z = blockIdx.z;
    const __half* A  = g_Ah + (size_t)(z ? 1 : 0) * 16384 * 512;
    const __half* Wt = g_Wt + (size_t)z * 512 * 512;

    const int m0 = blockIdx.y * 128;
    const int n0 = blockIdx.x * 128;

    extern __shared__ __align__(16) char psm[];
    const uint32_t aBase = (uint32_t)__cvta_generic_to_shared(psm);
    const uint32_t bBase = aBase + 32768;

    const int tid  = threadIdx.x;
    const int lane = tid & 31;
    const int wid  = tid >> 5;
    const int wm   = wid & 3;
    const int wn   = wid >> 2;

    float acc[2][8][4];
#pragma unroll
    for (int i = 0; i < 2; i++)
#pragma unroll
        for (int j = 0; j < 8; j++)
#pragma unroll
            for (int r = 0; r < 4; r++) acc[i][j][r] = 0.f;

    // staging: per k-step-64, 1024 16B-chunks per matrix; 4 per thread each.
    const int srow = tid >> 3;          // 0..31, +32*rr
    const int sc   = tid & 7;           // logical chunk 0..7
#define PROJ_ISSUE(kk, buf)                                                          \
    {                                                                                \
        _Pragma("unroll")                                                            \
        for (int rr = 0; rr < 4; rr++) {                                             \
            int row  = srow + rr * 32;                                               \
            int phys = sc ^ (row & 7);                                               \
            cp16(aBase + (buf) * 16384 + row * 128 + phys * 16,                      \
                 A + (size_t)(m0 + row) * 512 + (kk) * 64 + sc * 8);                 \
            cp16(bBase + (buf) * 16384 + row * 128 + phys * 16,                      \
                 Wt + (size_t)(n0 + row) * 512 + (kk) * 64 + sc * 8);                \
        }                                                                            \
    }

    PROJ_ISSUE(0, 0);
    CP_COMMIT();

    for (int it = 0; it < 8; it++) {
        CP_WAIT0();
        __syncthreads();
        const int buf = it & 1;
        if (it + 1 < 8) {
            PROJ_ISSUE(it + 1, buf ^ 1);
            CP_COMMIT();
        }

#pragma unroll
        for (int ss = 0; ss < 2; ss++) {
            uint32_t a[2][2][4];   // [kg][mi][]
#pragma unroll
            for (int kg = 0; kg < 2; kg++)
#pragma unroll
                for (int mi = 0; mi < 2; mi++) {
                    int row  = wm * 32 + mi * 16 + (lane & 15);
                    int c    = ss * 4 + kg * 2 + (lane >> 4);
                    int phys = c ^ (row & 7);
                    ldsm4(a[kg][mi][0], a[kg][mi][1], a[kg][mi][2], a[kg][mi][3],
                          aBase + buf * 16384 + row * 128 + phys * 16);
                }
#pragma unroll
            for (int ni = 0; ni < 8; ni++) {
                int row  = wn * 64 + ni * 8 + (lane & 7);
                int c    = ss * 4 + (lane >> 3);
                int phys = c ^ (row & 7);
                uint32_t b0, b1, b2, b3;
                ldsm4(b0, b1, b2, b3, bBase + buf * 16384 + row * 128 + phys * 16);
                mma_f16(acc[0][ni], a[0][0][0], a[0][0][1], a[0][0][2], a[0][0][3], b0, b1);
                mma_f16(acc[1][ni], a[0][1][0], a[0][1][1], a[0][1][2], a[0][1][3], b0, b1);
                mma_f16(acc[0][ni], a[1][0][0], a[1][0][1], a[1][0][2], a[1][0][3], b2, b3);
                mma_f16(acc[1][ni], a[1][1][0], a[1][1][1], a[1][1][2], a[1][1][3], b2, b3);
            }
        }
    }
#undef PROJ_ISSUE

    const int gid = lane >> 2;
    const int tig = lane & 3;

    if (z == 2) {
        // ---- V epilogue: stage [n][l] in smem, then coalesced 16B stores ----
        __syncthreads();   // all LDSM of last tile done; staging smem reusable
        __half* tsm = (__half*)psm;           // [128 n][136 l-stride]
#pragma unroll
        for (int mi = 0; mi < 2; mi++)
#pragma unroll
            for (int ni = 0; ni < 8; ni++) {
                int lr = wm * 32 + mi * 16 + gid;          // local row (l)
                int nc = wn * 64 + ni * 8 + tig * 2;       // local col (n)
#pragma unroll
                for (int rr = 0; rr < 2; rr++) {
                    int lrow = lr + rr * 8;
                    tsm[(nc + 0) * 136 + lrow] = __float2half_rn(acc[mi][ni][rr * 2 + 0]);
                    tsm[(nc + 1) * 136 + lrow] = __float2half_rn(acc[mi][ni][rr * 2 + 1]);
                }
            }
        __syncthreads();
        const int bb = m0 >> 9;
        const int l0 = m0 & 511;
#pragma unroll
        for (int itx = 0; itx < 8; itx++) {
            int e = tid + itx * 256;
            int n = e >> 4, cc = e & 15;
            uint4 v = *(const uint4*)&tsm[n * 136 + cc * 8];
            int gcol = n0 + n;
            int hh = gcol >> 6, dd = gcol & 63;
            *(uint4*)(g_Vt + ((size_t)(hh * 32 + bb) * 64 + dd) * 512 + l0 + cc * 8) = v;
        }
    } else {
        __half* dst = (z == 0) ? g_Qh : g_Kh;
        const float esc = (z == 0) ? EXPC : 1.f;   // fold softmax scale into Q
#pragma unroll
        for (int mi = 0; mi < 2; mi++)
#pragma unroll
            for (int ni = 0; ni < 8; ni++) {
                int gm = m0 + wm * 32 + mi * 16 + gid;
                int gn = n0 + wn * 64 + ni * 8 + tig * 2;
                int h = gn >> 6, d = gn & 63;
#pragma unroll
                for (int rr = 0; rr < 2; rr++) {
                    int row = gm + rr * 8;
                    int bb = row >> 9, ll = row & 511;
                    __half2 hv = __floats2half2_rn(acc[mi][ni][rr * 2 + 0] * esc,
                                                   acc[mi][ni][rr * 2 + 1] * esc);
                    *(__half2*)(dst + ((size_t)(h * 32 + bb) * 512 + ll) * 64 + d) = hv;
                }
            }
    }
}

// ---------------------------------------------------------------------------
// Kernel 4: fused flash attention. Q pre-scaled by EXPC, so S is already in
// the exp2 domain: fast path feeds mma output straight to ex2.approx.f16x2.
// Row sums via MMA against a constant all-ones B fragment. 2-stage KV prefetch.
// (byte-identical to the R14 passing version)
// ---------------------------------------------------------------------------
#define ATTN_SMEM_BYTES (size_t)((128 * 72 + 2 * 2 * 64 * 72) * 2)   // 55296

__global__ __launch_bounds__(256, 2) void attn_kernel(const float* __restrict__ query,
                                                      float* __restrict__ out) {
    const int hb = blockIdx.y;
    const int h  = hb >> 5;
    const int b  = hb & 31;
    const int m0 = blockIdx.x * 128;

    const __half* Qh = g_Qh + (size_t)hb * L_ * DH;
    const __half* Kh = g_Kh + (size_t)hb * L_ * DH;
    const __half* Vt = g_Vt + (size_t)hb * DH * L_;

    extern __shared__ __align__(16) __half dynsm[];
    const uint32_t qBase  = (uint32_t)__cvta_generic_to_shared(dynsm);
    const uint32_t kvBase = qBase + 128 * 72 * 2;
    const int KV_STAGE = 2 * 64 * 72 * 2;
    const int KV_VOFF  = 64 * 72 * 2;

    const int tid  = threadIdx.x;
    const int lane = tid & 31;
    const int wid  = tid >> 5;
    const int gid  = lane >> 2;
    const int tig  = lane & 3;
    const int q0   = m0 + wid * 16 + gid;
    const int q1   = q0 + 8;

    const int srow = tid >> 3;
    const int sc   = tid & 7;

#pragma unroll
    for (int r = 0; r < 4; r++) {
        int row = srow + r * 32;
        cp16(qBase + row * 144 + sc * 16, Qh + (size_t)(m0 + row) * 64 + sc * 8);
    }
    CP_COMMIT();

#define ATTN_ISSUE_KV(k0, st)                                                        \
    {                                                                                \
        _Pragma("unroll")                                                            \
        for (int r = 0; r < 2; r++) {                                                \
            int kc = srow + r * 32;                                                  \
            cp16(kvBase + (st) * KV_STAGE + kc * 144 + sc * 16,                      \
                 Kh + (size_t)((k0) + kc) * 64 + sc * 8);                            \
            cp16(kvBase + (st) * KV_STAGE + KV_VOFF + kc * 144 + sc * 16,            \
                 Vt + (size_t)kc * 512 + (k0) + sc * 8);                             \
        }                                                                            \
    }

    ATTN_ISSUE_KV(0, 0);
    CP_COMMIT();

    CP_WAIT1();
    __syncthreads();

    uint32_t Qa[4][4];
    {
        int row = wid * 16 + (lane & 15);
#pragma unroll
        for (int kg = 0; kg < 4; kg++) {
            int chunk = kg * 2 + (lane >> 4);
            ldsm4(Qa[kg][0], Qa[kg][1], Qa[kg][2], Qa[kg][3],
                  qBase + row * 144 + chunk * 16);
        }
    }

    float o[8][4];
#pragma unroll
    for (int di = 0; di < 8; di++)
#pragma unroll
        for (int j = 0; j < 4; j++) o[di][j] = 0.f;
    float lacc[4] = {0.f, 0.f, 0.f, 0.f};

    const int nkt = (m0 >> 6) + 2;
    for (int kt = 0; kt < nkt; kt++) {
        const int k0 = kt * 64;
        const int st = kt & 1;
        CP_WAIT0();
        __syncthreads();
        if (kt + 1 < nkt) {
            ATTN_ISSUE_KV(k0 + 64, st ^ 1);
            CP_COMMIT();
        }

        const uint32_t kB = kvBase + st * KV_STAGE;
        float s[8][4];
#pragma unroll
        for (int ni = 0; ni < 8; ni++)
#pragma unroll
            for (int j = 0; j < 4; j++) s[ni][j] = 0.f;
#pragma unroll
        for (int ni = 0; ni < 8; ni++) {
            uint32_t addr = kB + (ni * 8 + (lane & 7)) * 144 + (lane >> 3) * 16;
            uint32_t b0, b1, b2, b3, c0, c1, c2, c3;
            ldsm4(b0, b1, b2, b3, addr);
            ldsm4(c0, c1, c2, c3, addr + 64);
            mma_f16(s[ni], Qa[0][0], Qa[0][1], Qa[0][2], Qa[0][3], b0, b1);
            mma_f16(s[ni], Qa[1][0], Qa[1][1], Qa[1][2], Qa[1][3], b2, b3);
            mma_f16(s[ni], Qa[2][0], Qa[2][1], Qa[2][2], Qa[2][3], c0, c1);
            mma_f16(s[ni], Qa[3][0], Qa[3][1], Qa[3][2], Qa[3][3], c2, c3);
        }

        // Q was pre-scaled by EXPC, so s is already the exp2 exponent.
        const bool fast = g_kmflag[b * 8 + kt] && (k0 + 63 <= m0 + wid * 16);
        if (!fast) {
#pragma unroll
            for (int ni = 0; ni < 8; ni++) {
                int c0i = k0 + ni * 8 + tig * 2;
                bool km0 = g_km[b * 512 + c0i] != 0.f;
                bool km1 = g_km[b * 512 + c0i + 1] != 0.f;
                if (!(c0i <= q0     && km0)) s[ni][0] = -1e9f;
                if (!(c0i + 1 <= q0 && km1)) s[ni][1] = -1e9f;
                if (!(c0i <= q1     && km0)) s[ni][2] = -1e9f;
                if (!(c0i + 1 <= q1 && km1)) s[ni][3] = -1e9f;
            }
        }

        uint32_t Pa[4][4];
#pragma unroll
        for (int kg = 0; kg < 4; kg++) {
            Pa[kg][0] = ex2h2(h2u(s[2 * kg][0],     s[2 * kg][1]));
            Pa[kg][1] = ex2h2(h2u(s[2 * kg][2],     s[2 * kg][3]));
            Pa[kg][2] = ex2h2(h2u(s[2 * kg + 1][0], s[2 * kg + 1][1]));
            Pa[kg][3] = ex2h2(h2u(s[2 * kg + 1][2], s[2 * kg + 1][3]));
            mma_f16(lacc, Pa[kg][0], Pa[kg][1], Pa[kg][2], Pa[kg][3],
                    ONES_H2, ONES_H2);
        }

        const uint32_t vB = kB + KV_VOFF;
#pragma unroll
        for (int di = 0; di < 8; di++) {
            uint32_t addr = vB + (di * 8 + (lane & 7)) * 144 + (lane >> 3) * 16;
            uint32_t b0, b1, b2, b3, c0, c1, c2, c3;
            ldsm4(b0, b1, b2, b3, addr);
            ldsm4(c0, c1, c2, c3, addr + 64);
            mma_f16(o[di], Pa[0][0], Pa[0][1], Pa[0][2], Pa[0][3], b0, b1);
            mma_f16(o[di], Pa[1][0], Pa[1][1], Pa[1][2], Pa[1][3], b2, b3);
            mma_f16(o[di], Pa[2][0], Pa[2][1], Pa[2][2], Pa[2][3], c0, c1);
            mma_f16(o[di], Pa[3][0], Pa[3][1], Pa[3][2], Pa[3][3], c2, c3);
        }
    }
#undef ATTN_ISSUE_KV

    float sc0 = g_qm[b * 512 + q0] / lacc[0];
    float sc1 = g_qm[b * 512 + q1] / lacc[2];
#pragma unroll
    for (int di = 0; di < 8; di++) {
        int col = h * 64 + di * 8 + tig * 2;
        size_t i0 = ((size_t)(b * 512 + q0)) * 512 + col;
        size_t i1 = ((size_t)(b * 512 + q1)) * 512 + col;
        float2 qv0 = *(const float2*)(query + i0);
        float2 qv1 = *(const float2*)(query + i1);
        float2 w0, w1;
        w0.x = o[di][0] * sc0 + qv0.x;
        w0.y = o[di][1] * sc0 + qv0.y;
        w1.x = o[di][2] * sc1 + qv1.x;
        w1.y = o[di][3] * sc1 + qv1.y;
        *(float2*)(out + i0) = w0;
        *(float2*)(out + i1) = w1;
    }
}

// ---------------------------------------------------------------------------
// Launch
// ---------------------------------------------------------------------------
extern "C" void kernel_launch(void* const* d_in, const int* in_sizes, int n_in,
                              void* d_out, int out_size) {
    const float* query = (const float*)d_in[0];
    const float* key   = (const float*)d_in[1];
    const float* Wq    = (const float*)d_in[2];
    const float* Wk    = (const float*)d_in[3];
    const float* Wv    = (const float*)d_in[4];
    float* out = (float*)d_out;

    // Immediate (non-stream) API: capture-safe, idempotent, no allocation.
    cudaFuncSetAttribute(attn_kernel, cudaFuncAttributeMaxDynamicSharedMemorySize,
                         (int)ATTN_SMEM_BYTES);
    cudaFuncSetAttribute(proj_kernel, cudaFuncAttributeMaxDynamicSharedMemorySize,
                         (int)PROJ_SMEM_BYTES);

    prep_qk_kernel<<<4096, 256>>>(query, key);
    prep_flags_kernel<<<1, 256>>>();
    prep_w_kernel<<<dim3(16, 16, 3), 256>>>(Wq, Wk, Wv);
    proj_kernel<<<dim3(4, 128, 3), 256, PROJ_SMEM_BYTES>>>();
    attn_kernel<<<dim3(4, HB), 256, ATTN_SMEM_BYTES>>>(query, out);
}